// round 16
// baseline (speedup 1.0000x reference)
#include <cuda_runtime.h>
#include <cuda_fp16.h>
#include <math.h>
#include <stdint.h>

// ---------------- problem constants ----------------
#define N0v 100000
#define N1v 20000
#define N2v 4000
#define E0v 160000
#define E1v 64000

// ---------------- device scratch ----------------
__device__ __align__(16) __half g_feat0[(size_t)N0v * 256];
__device__ __align__(16) __half g_feat1[(size_t)N1v * 256];
__device__ __align__(16) __half g_msg[(size_t)3 * N1v * 768];
__device__ __align__(16) __half g_z[(size_t)3 * N1v * 128];
__device__ __align__(16) __half g_xh[(size_t)N0v * 128];
__device__ int    g_cnt0[3 * N1v];
__device__ int    g_off0[3 * N1v + 1];
__device__ int    g_cur0[3 * N1v];
__device__ int    g_sorted0[3 * E0v];
__device__ int    g_bsum0[128];
__device__ int    g_cnt1[3 * N2v];
__device__ int    g_off1[3 * N2v + 1];
__device__ int    g_cur1[3 * N2v];
__device__ int    g_sorted1[3 * E1v];
__device__ int    g_bsum1[128];
__device__ float  g_partial[8192];
__device__ float  g_beta[4];
__device__ int    g_ctr0;
__device__ int    g_ctr1;
__device__ __align__(16) __half g_bt[1015808];  // all weights, transposed fp16 K-major [128,K]

#define BT_EMBED 0
#define BT_ATTN  16384
#define BT_L1F1  32768
#define BT_L1F2  131072
#define BT_L1F3  425984
#define BT_L2F1  524288
#define BT_L2F2  622592
#define BT_L2F3  917504
#define BT_TOTAL 1015808

#define PAD  40    // pipeline tile row stride (halves)
#define INPS 264   // inpS row stride (halves)

__device__ __forceinline__ uint32_t smem_u32(const void* p) {
    uint32_t a;
    asm("{ .reg .u64 t; cvta.to.shared.u64 t, %1; cvt.u32.u64 %0, t; }" : "=r"(a) : "l"(p));
    return a;
}
__device__ __forceinline__ void mma_f16(float* d, const uint32_t* a, const uint32_t* b) {
    asm volatile(
        "mma.sync.aligned.m16n8k16.row.col.f32.f16.f16.f32 "
        "{%0,%1,%2,%3},{%4,%5,%6,%7},{%8,%9},{%0,%1,%2,%3};"
        : "+f"(d[0]), "+f"(d[1]), "+f"(d[2]), "+f"(d[3])
        : "r"(a[0]), "r"(a[1]), "r"(a[2]), "r"(a[3]), "r"(b[0]), "r"(b[1]));
}
__device__ __forceinline__ void ldsm_x4(uint32_t* r, uint32_t addr) {
    asm volatile("ldmatrix.sync.aligned.m8n8.x4.shared.b16 {%0,%1,%2,%3}, [%4];"
        : "=r"(r[0]), "=r"(r[1]), "=r"(r[2]), "=r"(r[3]) : "r"(addr));
}
__device__ __forceinline__ void ldsm_x2(uint32_t* r, uint32_t addr) {
    asm volatile("ldmatrix.sync.aligned.m8n8.x2.shared.b16 {%0,%1}, [%2];"
        : "=r"(r[0]), "=r"(r[1]) : "r"(addr));
}
__device__ __forceinline__ void cp16(uint32_t dst, const void* src, int sz) {
    asm volatile("cp.async.cg.shared.global [%0], [%1], 16, %2;"
        :: "r"(dst), "l"(src), "r"(sz));
}
#define CP_COMMIT() asm volatile("cp.async.commit_group;")

// ---------------- prep: all weights -> transposed fp16 table ----------------
__global__ void prep_all(const float* __restrict__ ew, const float* __restrict__ aw,
                         const float* __restrict__ f11, const float* __restrict__ f12,
                         const float* __restrict__ f13, const float* __restrict__ f21,
                         const float* __restrict__ f22, const float* __restrict__ f23,
                         __half* __restrict__ bt)
{
    int i = blockIdx.x * 256 + threadIdx.x;
    if (i >= BT_TOTAL) return;
    const float* w; int K; int rem;
    if (i < BT_ATTN)      { w = ew;  K = 128; rem = i - BT_EMBED; }
    else if (i < BT_L1F1) { w = aw;  K = 128; rem = i - BT_ATTN; }
    else if (i < BT_L1F2) { w = f11; K = 256; rem = i - BT_L1F1; }
    else if (i < BT_L1F3) { w = f12; K = 768; rem = i - BT_L1F2; }
    else if (i < BT_L2F1) { w = f13; K = 256; rem = i - BT_L1F3; }
    else if (i < BT_L2F2) { w = f21; K = 256; rem = i - BT_L2F1; }
    else if (i < BT_L2F3) { w = f22; K = 768; rem = i - BT_L2F2; }
    else                  { w = f23; K = 256; rem = i - BT_L2F3; }
    int per = 128 * K;
    int r = rem / per, j = rem - r * per;
    int n = j / K, k = j - n * K;
    bt[i] = __float2half_rn(w[(size_t)r * per + (size_t)k * 128 + n]);
}

// ---------------- fp32 -> fp16 vector convert ----------------
__global__ void cvt_x(const float4* __restrict__ x, __half2* __restrict__ xh, int n4)
{
    int i = blockIdx.x * 256 + threadIdx.x;
    if (i < n4) {
        float4 v = x[i];
        xh[2 * i]     = __floats2half2_rn(v.x, v.y);
        xh[2 * i + 1] = __floats2half2_rn(v.z, v.w);
    }
}

// ---------------- gather tss/rs into feat cols [128:256) ----------------
__global__ void gather_emb(const float* __restrict__ tss, const float* __restrict__ rs,
                           const int* __restrict__ nid, __half* __restrict__ feat, int n)
{
    int i = blockIdx.x * blockDim.x + threadIdx.x;
    int row = i >> 7, c = i & 127;
    if (row < n) {
        int g = nid[row];
        float v = (c < 64) ? tss[(size_t)g * 64 + c] : rs[(size_t)g * 64 + (c - 64)];
        feat[(size_t)row * 256 + 128 + c] = __float2half_rn(v);
    }
}

// ---------------- pipelined GEMM mainloops ----------------
template <int MT, int NTL>
__device__ __forceinline__ void gemm_gA(
    const __half* __restrict__ A, int lda, const __half* __restrict__ B, int K,
    int M, int m0, float acc[2][NTL][4], __half* pA, __half* pB,
    int tid, int wm, int wn, int a_m, int a_k, int b_n, int b_k)
{
    const int nt = K >> 5;
    const int lr = tid >> 2, lch = (tid & 3) * 8;
    const uint32_t pA0 = smem_u32(pA), pB0 = smem_u32(pB);
#pragma unroll
    for (int l = 0; l < MT / 64; l++) {
        int r = lr + l * 64;
        int gr = m0 + r;
        int sz = (gr < M) ? 16 : 0;
        cp16(pA0 + (r * PAD + lch) * 2, A + (size_t)(sz ? gr : m0) * lda + lch, sz);
    }
#pragma unroll
    for (int l = 0; l < 2; l++) {
        int r = lr + l * 64;
        cp16(pB0 + (r * PAD + lch) * 2, B + (size_t)r * K + lch, 16);
    }
    CP_COMMIT();
    for (int t = 0; t < nt; t++) {
        const int buf = t & 1;
        if (t + 1 < nt) {
            const int nb2 = (t + 1) & 1;
            int k0 = (t + 1) << 5;
#pragma unroll
            for (int l = 0; l < MT / 64; l++) {
                int r = lr + l * 64;
                int gr = m0 + r;
                int sz = (gr < M) ? 16 : 0;
                cp16(pA0 + (nb2 * MT * PAD + r * PAD + lch) * 2,
                     A + (size_t)(sz ? gr : m0) * lda + k0 + lch, sz);
            }
#pragma unroll
            for (int l = 0; l < 2; l++) {
                int r = lr + l * 64;
                cp16(pB0 + (nb2 * 128 * PAD + r * PAD + lch) * 2,
                     B + (size_t)r * K + k0 + lch, 16);
            }
            CP_COMMIT();
            asm volatile("cp.async.wait_group 1;");
        } else {
            asm volatile("cp.async.wait_group 0;");
        }
        __syncthreads();
#pragma unroll
        for (int ks = 0; ks < 2; ks++) {
            const int kk = ks * 16;
            uint32_t af[2][4];
#pragma unroll
            for (int mt = 0; mt < 2; mt++)
                ldsm_x4(af[mt], smem_u32(&pA[buf * MT * PAD + (wm * 32 + mt * 16 + a_m) * PAD + kk + a_k]));
#pragma unroll
            for (int ntl = 0; ntl < NTL; ntl++) {
                uint32_t bf[2];
                ldsm_x2(bf, smem_u32(&pB[buf * 128 * PAD + (wn * (NTL * 8) + ntl * 8 + b_n) * PAD + kk + b_k]));
#pragma unroll
                for (int mt = 0; mt < 2; mt++)
                    mma_f16(acc[mt][ntl], af[mt], bf);
            }
        }
        __syncthreads();
    }
}

// A resident in smem (inpS, stride INPS), BK=32 B pipeline
template <int MT, int NTL>
__device__ __forceinline__ void gemm_sA(
    const __half* sAfull, const __half* __restrict__ B, int K,
    float acc[2][NTL][4], __half* pB,
    int tid, int wm, int wn, int a_m, int a_k, int b_n, int b_k)
{
    const int nt = K >> 5;
    const int lr = tid >> 2, lch = (tid & 3) * 8;
    const uint32_t pB0 = smem_u32(pB);
#pragma unroll
    for (int l = 0; l < 2; l++) {
        int r = lr + l * 64;
        cp16(pB0 + (r * PAD + lch) * 2, B + (size_t)r * K + lch, 16);
    }
    CP_COMMIT();
    for (int t = 0; t < nt; t++) {
        const int buf = t & 1;
        if (t + 1 < nt) {
            const int nb2 = (t + 1) & 1;
            int k0 = (t + 1) << 5;
#pragma unroll
            for (int l = 0; l < 2; l++) {
                int r = lr + l * 64;
                cp16(pB0 + (nb2 * 128 * PAD + r * PAD + lch) * 2,
                     B + (size_t)r * K + k0 + lch, 16);
            }
            CP_COMMIT();
            asm volatile("cp.async.wait_group 1;");
        } else {
            asm volatile("cp.async.wait_group 0;");
        }
        __syncthreads();
#pragma unroll
        for (int ks = 0; ks < 2; ks++) {
            const int kk = ks * 16;
            uint32_t af[2][4];
#pragma unroll
            for (int mt = 0; mt < 2; mt++)
                ldsm_x4(af[mt], smem_u32(&sAfull[(wm * 32 + mt * 16 + a_m) * INPS + t * 32 + kk + a_k]));
#pragma unroll
            for (int ntl = 0; ntl < NTL; ntl++) {
                uint32_t bf[2];
                ldsm_x2(bf, smem_u32(&pB[buf * 128 * PAD + (wn * (NTL * 8) + ntl * 8 + b_n) * PAD + kk + b_k]));
#pragma unroll
                for (int mt = 0; mt < 2; mt++)
                    mma_f16(acc[mt][ntl], af[mt], bf);
            }
        }
        __syncthreads();
    }
}

#define ZERO_ACC(acc, NTL) do { \
    _Pragma("unroll") for (int _i = 0; _i < 2; _i++) \
    _Pragma("unroll") for (int _j = 0; _j < NTL; _j++) \
    _Pragma("unroll") for (int _q = 0; _q < 4; _q++) acc[_i][_j][_q] = 0.f; } while (0)

// ---------------- fused IGConv + attention dot + last-CTA beta ----------------
// MT=64 with 3 CTAs/SM (24 warps/SM) for latency hiding; MT=128 instance kept at 2/SM.
template <int MT, int OCC>
__global__ void __launch_bounds__(256, OCC) igconv(
    const __half* __restrict__ msg, const __half* __restrict__ feat,
    const __half* __restrict__ w2t, const __half* __restrict__ w1t,
    const __half* __restrict__ w3t, const __half* __restrict__ wat,
    const float* __restrict__ b2, const float* __restrict__ b1,
    const float* __restrict__ b3, const float* __restrict__ ba,
    const float* __restrict__ w2a,
    __half* __restrict__ z, float* __restrict__ partial,
    float* __restrict__ beta_out, int* __restrict__ ctr, float invN,
    int M, int nbx)
{
    constexpr int NWM = MT / 32;
    constexpr int NWN = 8 / NWM;
    constexpr int NTL = 128 / (NWN * 8);

    extern __shared__ __half sm[];
    __half* inpS = sm;                         // MT x INPS
    __half* pA   = sm + MT * INPS;             // 2 x MT x PAD
    __half* pB   = pA + 2 * MT * PAD;          // 2 x 128 x PAD
    float* rowsum = (float*)pA;

    __shared__ float bsh[3];
    __shared__ int lastFlag;

    const int tid = threadIdx.x, wid = tid >> 5, lane = tid & 31;
    const int wm = wid & (NWM - 1), wn = wid / NWM;
    const int rrel = blockIdx.y;
    const int m0 = blockIdx.x * MT;
    const int a_m = (lane & 7) + ((lane >> 3) & 1) * 8;
    const int a_k = (lane >> 4) * 8;
    const int bln = lane & 15;
    const int b_n = bln & 7;
    const int b_k = ((bln >> 3) & 1) * 8;
    const int fr = lane >> 2, fc = (lane & 3) * 2;

    float acc[2][NTL][4];

    // ---- stage 1: fc2 (msg @ W2) -> relu -> inpS[:,0:128) ----
    ZERO_ACC(acc, NTL);
    gemm_gA<MT, NTL>(msg + (size_t)rrel * M * 768, 768, w2t + (size_t)rrel * 128 * 768, 768,
                     M, m0, acc, pA, pB, tid, wm, wn, a_m, a_k, b_n, b_k);
    {
        const float* bb = b2 + rrel * 128;
#pragma unroll
        for (int mt = 0; mt < 2; mt++)
#pragma unroll
            for (int hf = 0; hf < 2; hf++) {
                int row = wm * 32 + mt * 16 + fr + hf * 8;
#pragma unroll
                for (int ntl = 0; ntl < NTL; ntl++) {
                    int gc = wn * (NTL * 8) + ntl * 8 + fc;
                    float vx = fmaxf(acc[mt][ntl][hf * 2 + 0] + bb[gc + 0], 0.f);
                    float vy = fmaxf(acc[mt][ntl][hf * 2 + 1] + bb[gc + 1], 0.f);
                    *(__half2*)&inpS[row * INPS + gc] = __floats2half2_rn(vx, vy);
                }
            }
    }

    // ---- stage 2: fc1 (feat @ W1) -> relu -> inpS[:,128:256) ----
    ZERO_ACC(acc, NTL);
    gemm_gA<MT, NTL>(feat, 256, w1t + (size_t)rrel * 128 * 256, 256,
                     M, m0, acc, pA, pB, tid, wm, wn, a_m, a_k, b_n, b_k);
    {
        const float* bb = b1 + rrel * 128;
#pragma unroll
        for (int mt = 0; mt < 2; mt++)
#pragma unroll
            for (int hf = 0; hf < 2; hf++) {
                int row = wm * 32 + mt * 16 + fr + hf * 8;
#pragma unroll
                for (int ntl = 0; ntl < NTL; ntl++) {
                    int gc = wn * (NTL * 8) + ntl * 8 + fc;
                    float vx = fmaxf(acc[mt][ntl][hf * 2 + 0] + bb[gc + 0], 0.f);
                    float vy = fmaxf(acc[mt][ntl][hf * 2 + 1] + bb[gc + 1], 0.f);
                    *(__half2*)&inpS[row * INPS + 128 + gc] = __floats2half2_rn(vx, vy);
                }
            }
    }
    __syncthreads();

    // ---- stage 3: fc3 (inpS @ W3) -> z (fp16) + zh into inpS[:,0:128) ----
    ZERO_ACC(acc, NTL);
    gemm_sA<MT, NTL>(inpS, w3t + (size_t)rrel * 128 * 256, 256,
                     acc, pB, tid, wm, wn, a_m, a_k, b_n, b_k);
    {
        const float* bb = b3 + rrel * 128;
        __half* zr = z + (size_t)rrel * M * 128;
#pragma unroll
        for (int mt = 0; mt < 2; mt++)
#pragma unroll
            for (int hf = 0; hf < 2; hf++) {
                int row = wm * 32 + mt * 16 + fr + hf * 8;
                int gr = m0 + row;
#pragma unroll
                for (int ntl = 0; ntl < NTL; ntl++) {
                    int gc = wn * (NTL * 8) + ntl * 8 + fc;
                    float vx = acc[mt][ntl][hf * 2 + 0] + bb[gc + 0];
                    float vy = acc[mt][ntl][hf * 2 + 1] + bb[gc + 1];
                    __half2 h = __floats2half2_rn(vx, vy);
                    if (gr < M) *(__half2*)&zr[(size_t)gr * 128 + gc] = h;
                    *(__half2*)&inpS[row * INPS + gc] = h;
                }
            }
    }
    __syncthreads();

    // ---- stage 4: attention (zh @ attnW1) -> tanh -> dot w2 -> partial ----
    ZERO_ACC(acc, NTL);
    gemm_sA<MT, NTL>(inpS, wat, 128, acc, pB, tid, wm, wn, a_m, a_k, b_n, b_k);
#pragma unroll
    for (int mt = 0; mt < 2; mt++)
#pragma unroll
        for (int hf = 0; hf < 2; hf++) {
            int row = wm * 32 + mt * 16 + fr + hf * 8;
            int gr = m0 + row;
            float acc_s = 0.f;
            if (gr < M) {
#pragma unroll
                for (int ntl = 0; ntl < NTL; ntl++) {
                    int gc = wn * (NTL * 8) + ntl * 8 + fc;
                    float vx = tanhf(acc[mt][ntl][hf * 2 + 0] + ba[gc + 0]);
                    float vy = tanhf(acc[mt][ntl][hf * 2 + 1] + ba[gc + 1]);
                    acc_s += vx * w2a[gc] + vy * w2a[gc + 1];
                }
            }
            float v = acc_s;
            v += __shfl_xor_sync(0xFFFFFFFFu, v, 1);
            v += __shfl_xor_sync(0xFFFFFFFFu, v, 2);
            if ((lane & 3) == 0) rowsum[wn * MT + row] = v;
        }
    __syncthreads();
    if (wid == 0) {
        float tot = 0.f;
        for (int i = lane; i < NWN * MT; i += 32) tot += rowsum[i];
#pragma unroll
        for (int o = 16; o; o >>= 1) tot += __shfl_xor_sync(0xFFFFFFFFu, tot, o);
        if (!lane) {
            partial[rrel * nbx + blockIdx.x] = tot;
            __threadfence();
            int old = atomicAdd(ctr, 1);
            lastFlag = (old == 3 * nbx - 1) ? 1 : 0;
        }
    }
    __syncthreads();
    if (lastFlag) {
        __threadfence();
        if (tid < 3) {
            float s = 0.f;
            for (int i = 0; i < nbx; i++) s += partial[tid * nbx + i];
            bsh[tid] = s * invN;
        }
        __syncthreads();
        if (tid == 0) {
            float m = fmaxf(bsh[0], fmaxf(bsh[1], bsh[2]));
            float e0 = expf(bsh[0] - m), e1 = expf(bsh[1] - m), e2 = expf(bsh[2] - m);
            float inv = 1.f / (e0 + e1 + e2);
            beta_out[0] = e0 * inv; beta_out[1] = e1 * inv; beta_out[2] = e2 * inv;
            *ctr = 0;
            __threadfence();
        }
    }
}

// ---------------- embed HGEMM (fp16 A, cp.async; cols [0:128) only) ----------------
__global__ void __launch_bounds__(256, 2) embed_gemm(
    const __half* __restrict__ A, const __half* __restrict__ B,
    const float* __restrict__ bias, __half* __restrict__ C, int M)
{
    __shared__ __align__(16) __half sA[2][128 * PAD];
    __shared__ __align__(16) __half sB[2][128 * PAD];
    const int tid = threadIdx.x, wid = tid >> 5, lane = tid & 31;
    const int wm = wid & 3, wn = wid >> 2;
    const int m0 = blockIdx.x * 128;
    const int a_m = (lane & 7) + ((lane >> 3) & 1) * 8;
    const int a_k = (lane >> 4) * 8;
    const int bln = lane & 15;
    const int b_n = bln & 7;
    const int b_k = ((bln >> 3) & 1) * 8;
    float acc[2][8][4];
    ZERO_ACC(acc, 8);
    gemm_gA<128, 8>(A, 128, B, 128, M, m0, acc, sA[0], sB[0], tid, wm, wn, a_m, a_k, b_n, b_k);
    const int fr = lane >> 2, fc = (lane & 3) * 2;
#pragma unroll
    for (int mt = 0; mt < 2; mt++)
#pragma unroll
        for (int hf = 0; hf < 2; hf++) {
            int gr = m0 + wm * 32 + mt * 16 + fr + hf * 8;
            if (gr >= M) continue;
#pragma unroll
            for (int ntl = 0; ntl < 8; ntl++) {
                int gc = wn * 64 + ntl * 8 + fc;
                float vx = acc[mt][ntl][hf * 2 + 0] + bias[gc + 0];
                float vy = acc[mt][ntl][hf * 2 + 1] + bias[gc + 1];
                *(__half2*)&C[(size_t)gr * 256 + gc] = __floats2half2_rn(vx, vy);
            }
        }
}

// ---------------- CSR build ----------------
__global__ void hist_k(const int* __restrict__ dst, int* __restrict__ cnt, int E, int ndst)
{
    int e = blockIdx.x * blockDim.x + threadIdx.x;
    if (e < 3 * E) atomicAdd(&cnt[(e / E) * ndst + dst[e]], 1);
}
__global__ void scan_part(const int* __restrict__ cnt, int* __restrict__ off,
                          int* __restrict__ bsum, int n)
{
    __shared__ int ws[32];
    int tid = threadIdx.x, lane = tid & 31, w = tid >> 5;
    int i = blockIdx.x * 1024 + tid;
    int v = (i < n) ? cnt[i] : 0;
    int x = v;
#pragma unroll
    for (int o = 1; o < 32; o <<= 1) {
        int t = __shfl_up_sync(0xFFFFFFFFu, x, o);
        if (lane >= o) x += t;
    }
    if (lane == 31) ws[w] = x;
    __syncthreads();
    if (w == 0) {
        int y = ws[lane];
#pragma unroll
        for (int o = 1; o < 32; o <<= 1) {
            int t = __shfl_up_sync(0xFFFFFFFFu, y, o);
            if (lane >= o) y += t;
        }
        ws[lane] = y;
    }
    __syncthreads();
    int excl = x - v + (w ? ws[w - 1] : 0);
    if (i < n) off[i] = excl;
    if (tid == 1023) bsum[blockIdx.x] = excl + v;
}
__global__ void scan_bs(int* __restrict__ bsum, int* __restrict__ off, int nb, int n)
{
    __shared__ int sh[64];
    int tid = threadIdx.x;
    int v = (tid < nb) ? bsum[tid] : 0;
    sh[tid] = v;
    __syncthreads();
    for (int d = 1; d < 64; d <<= 1) {
        int t = (tid >= d) ? sh[tid - d] : 0;
        __syncthreads();
        sh[tid] += t;
        __syncthreads();
    }
    if (tid < nb) bsum[tid] = sh[tid] - v;
    if (tid == 0) off[n] = sh[63];
}
__global__ void scan_add(int* __restrict__ off, const int* __restrict__ bsum,
                         int* __restrict__ cur, int n)
{
    int i = blockIdx.x * 1024 + threadIdx.x;
    if (i < n) {
        int o = off[i] + bsum[blockIdx.x];
        off[i] = o;
        cur[i] = o;
    }
}
__global__ void scatter_k(const int* __restrict__ src, const int* __restrict__ dst,
                          int* __restrict__ cur, int* __restrict__ sorted, int E, int ndst)
{
    int e = blockIdx.x * blockDim.x + threadIdx.x;
    if (e < 3 * E) {
        int p = atomicAdd(&cur[(e / E) * ndst + dst[e]], 1);
        sorted[p] = src[e];
    }
}

// ---------------- aggregation: warp per (rel,dst) ----------------
#define DEGCAP 96
__global__ void aggregate_w(const __half* __restrict__ feat, const int* __restrict__ off,
                            const int* __restrict__ sorted, __half* __restrict__ msg)
{
    __shared__ int idx[8][DEGCAP];
    int ws = threadIdx.x >> 5, lane = threadIdx.x & 31;
    int b = blockIdx.x * 8 + ws;
    int s0 = off[b];
    int deg = off[b + 1] - s0;
    if (deg > DEGCAP) deg = DEGCAP;
    for (int i = lane; i < deg; i += 32) idx[ws][i] = sorted[s0 + i];
    __syncwarp();
    for (int p = 0; p < deg; p++) {
        for (int j = (p & 1) + 2 * lane; j + 1 < deg; j += 64) {
            int a = idx[ws][j], c = idx[ws][j + 1];
            if (a > c) { idx[ws][j] = c; idx[ws][j + 1] = a; }
        }
        __syncwarp();
    }
    float sum[8], mx[8];
#pragma unroll
    for (int q = 0; q < 8; q++) { sum[q] = 0.f; mx[q] = -INFINITY; }
    for (int i = 0; i < deg; i++) {
        uint4 v = *(const uint4*)(feat + (size_t)idx[ws][i] * 256 + lane * 8);
        __half2* h = (__half2*)&v;
#pragma unroll
        for (int q = 0; q < 4; q++) {
            float2 f = __half22float2(h[q]);
            sum[2 * q]     += f.x;
            sum[2 * q + 1] += f.y;
            mx[2 * q]       = fmaxf(mx[2 * q], f.x);
            mx[2 * q + 1]   = fmaxf(mx[2 * q + 1], f.y);
        }
    }
    float inv = deg ? 1.f / (float)deg : 0.f;
    if (!deg) {
#pragma unroll
        for (int q = 0; q < 8; q++) mx[q] = 0.f;
    }
    __half2 omx[4], omean[4], osum[4];
#pragma unroll
    for (int q = 0; q < 4; q++) {
        omx[q]   = __floats2half2_rn(mx[2 * q], mx[2 * q + 1]);
        omean[q] = __floats2half2_rn(sum[2 * q] * inv, sum[2 * q + 1] * inv);
        osum[q]  = __floats2half2_rn(sum[2 * q], sum[2 * q + 1]);
    }
    size_t base = (size_t)b * 768 + lane * 8;
    *(uint4*)(msg + base)       = *(uint4*)omx;
    *(uint4*)(msg + base + 256) = *(uint4*)omean;
    *(uint4*)(msg + base + 512) = *(uint4*)osum;
}

// ---------------- layer0 combine (vectorized: 2 cols/thread) ----------------
__global__ void combine_gather(const __half2* __restrict__ z, const float* __restrict__ beta,
                               __half2* __restrict__ feat, int n, int zstride2)
{
    int i = blockIdx.x * blockDim.x + threadIdx.x;   // n*64 jobs
    int row = i >> 6, c2 = i & 63;
    if (row >= n) return;
    float b0 = __ldg(&beta[0]), b1 = __ldg(&beta[1]), b2 = __ldg(&beta[2]);
    size_t o = (size_t)row * 64 + c2;
    float2 z0 = __half22float2(z[o]);
    float2 z1 = __half22float2(z[o + (size_t)zstride2]);
    float2 z2 = __half22float2(z[o + 2 * (size_t)zstride2]);
    float vx = fmaxf(b0 * z0.x + b1 * z1.x + b2 * z2.x, 0.f);
    float vy = fmaxf(b0 * z0.y + b1 * z1.y + b2 * z2.y, 0.f);
    feat[(size_t)row * 128 + c2] = __floats2half2_rn(vx, vy);
}

// ---------------- layer1 combine + predictor ----------------
__global__ void combine_pred(const __half* __restrict__ z, const float* __restrict__ beta,
                             const float* __restrict__ pw, const float* __restrict__ pb,
                             float* __restrict__ out, int n, int zstride)
{
    __shared__ float sh[4];
    int row = blockIdx.x, c = threadIdx.x;
    float b0 = __ldg(&beta[0]), b1 = __ldg(&beta[1]), b2 = __ldg(&beta[2]);
    size_t o = (size_t)row * 128 + c;
    float v = b0 * __half2float(z[o]) + b1 * __half2float(z[o + (size_t)zstride])
            + b2 * __half2float(z[o + 2 * (size_t)zstride]);
    float s = v * pw[c];
    int lane = c & 31, w = c >> 5;
#pragma unroll
    for (int of = 16; of; of >>= 1) s += __shfl_xor_sync(0xFFFFFFFFu, s, of);
    if (!lane) sh[w] = s;
    __syncthreads();
    if (c == 0) {
        float tot = sh[0] + sh[1] + sh[2] + sh[3];
        out[row] = 1.f / (1.f + expf(-(tot + pb[0])));
    }
}

// ---------------- host orchestration ----------------
static inline int cdiv(int a, int b) { return (a + b - 1) / b; }
#define IG_SMEM_64  ((64 * INPS + 2 * 64 * PAD + 2 * 128 * PAD) * 2)

extern "C" void kernel_launch(void* const* d_in, const int* in_sizes, int n_in,
                              void* d_out, int out_size)
{
    const float* x_user   = (const float*)d_in[0];
    const float* tss      = (const float*)d_in[1];
    const float* rs       = (const float*)d_in[2];
    const int*   src_nid0 = (const int*)d_in[3];
    const int*   src_nid1 = (const int*)d_in[4];
    const int*   e0_src   = (const int*)d_in[5];
    const int*   e0_dst   = (const int*)d_in[6];
    const int*   e1_src   = (const int*)d_in[7];
    const int*   e1_dst   = (const int*)d_in[8];
    const float* embed_w  = (const float*)d_in[9];
    const float* embed_b  = (const float*)d_in[10];
    const float* attn_w1  = (const float*)d_in[23];
    const float* attn_b1  = (const float*)d_in[24];
    const float* attn_w2  = (const float*)d_in[25];
    const float* pred_w   = (const float*)d_in[26];
    const float* pred_b   = (const float*)d_in[27];
    float* out = (float*)d_out;

    __half *feat0, *feat1, *msg, *bt, *xh, *z;
    float *partial, *beta;
    int *ctr0, *ctr1;
    int *cnt0, *off0, *cur0, *sorted0, *bsum0;
    int *cnt1, *off1, *cur1, *sorted1, *bsum1;
    cudaGetSymbolAddress((void**)&feat0, g_feat0);
    cudaGetSymbolAddress((void**)&feat1, g_feat1);
    cudaGetSymbolAddress((void**)&msg, g_msg);
    cudaGetSymbolAddress((void**)&z, g_z);
    cudaGetSymbolAddress((void**)&xh, g_xh);
    cudaGetSymbolAddress((void**)&partial, g_partial);
    cudaGetSymbolAddress((void**)&beta, g_beta);
    cudaGetSymbolAddress((void**)&ctr0, g_ctr0);
    cudaGetSymbolAddress((void**)&ctr1, g_ctr1);
    cudaGetSymbolAddress((void**)&cnt0, g_cnt0);
    cudaGetSymbolAddress((void**)&off0, g_off0);
    cudaGetSymbolAddress((void**)&cur0, g_cur0);
    cudaGetSymbolAddress((void**)&sorted0, g_sorted0);
    cudaGetSymbolAddress((void**)&bsum0, g_bsum0);
    cudaGetSymbolAddress((void**)&cnt1, g_cnt1);
    cudaGetSymbolAddress((void**)&off1, g_off1);
    cudaGetSymbolAddress((void**)&cur1, g_cur1);
    cudaGetSymbolAddress((void**)&sorted1, g_sorted1);
    cudaGetSymbolAddress((void**)&bsum1, g_bsum1);
    cudaGetSymbolAddress((void**)&bt, g_bt);

    static cudaStream_t sA = 0, sB = 0;
    static cudaEvent_t ev[8];
    static bool init = false;
    if (!init) {
        cudaStreamCreateWithFlags(&sA, cudaStreamNonBlocking);
        cudaStreamCreateWithFlags(&sB, cudaStreamNonBlocking);
        for (int i = 0; i < 8; i++) cudaEventCreateWithFlags(&ev[i], cudaEventDisableTiming);
        cudaFuncSetAttribute((const void*)igconv<64, 3>,
                             cudaFuncAttributeMaxDynamicSharedMemorySize, IG_SMEM_64);
        init = true;
    }

    const int n0 = 3 * N1v, nb0 = cdiv(n0, 1024);
    const int n1 = 3 * N2v, nb1 = cdiv(n1, 1024);
    const int nbx0 = cdiv(N1v, 64), nbx1 = cdiv(N2v, 64);

    // fork
    cudaEventRecord(ev[0], 0);
    cudaStreamWaitEvent(sA, ev[0], 0);
    cudaStreamWaitEvent(sB, ev[0], 0);

    // sA: x convert -> feat0 gather (cols [128:256)) -> CSR0
    cvt_x<<<cdiv(N0v * 128 / 4, 256), 256, 0, sA>>>(
        (const float4*)x_user, (__half2*)xh, N0v * 128 / 4);
    cudaEventRecord(ev[3], sA);
    gather_emb<<<cdiv(N0v * 128, 256), 256, 0, sA>>>(tss, rs, src_nid0, feat0, N0v);
    cudaMemsetAsync(cnt0, 0, n0 * sizeof(int), sA);
    hist_k<<<cdiv(3 * E0v, 256), 256, 0, sA>>>(e0_dst, cnt0, E0v, N1v);
    scan_part<<<nb0, 1024, 0, sA>>>(cnt0, off0, bsum0, n0);
    scan_bs<<<1, 64, 0, sA>>>(bsum0, off0, nb0, n0);
    scan_add<<<nb0, 1024, 0, sA>>>(off0, bsum0, cur0, n0);
    scatter_k<<<cdiv(3 * E0v, 256), 256, 0, sA>>>(e0_src, e0_dst, cur0, sorted0, E0v, N1v);
    cudaEventRecord(ev[1], sA);   // CSR0 + feat0 gather done

    // sB: feat1 gather (cols [128:256)) -> CSR1
    gather_emb<<<cdiv(N1v * 128, 256), 256, 0, sB>>>(tss, rs, src_nid1, feat1, N1v);
    cudaMemsetAsync(cnt1, 0, n1 * sizeof(int), sB);
    hist_k<<<cdiv(3 * E1v, 256), 256, 0, sB>>>(e1_dst, cnt1, E1v, N2v);
    scan_part<<<nb1, 1024, 0, sB>>>(cnt1, off1, bsum1, n1);
    scan_bs<<<1, 64, 0, sB>>>(bsum1, off1, nb1, n1);
    scan_add<<<nb1, 1024, 0, sB>>>(off1, bsum1, cur1, n1);
    scatter_k<<<cdiv(3 * E1v, 256), 256, 0, sB>>>(e1_src, e1_dst, cur1, sorted1, E1v, N2v);
    cudaEventRecord(ev[2], sB);   // CSR1 + feat1 gather done

    // stream 0: weight prep; embed GEMM (cols [0:128) only)
    prep_all<<<cdiv(BT_TOTAL, 256), 256>>>(
        embed_w, attn_w1,
        (const float*)d_in[11], (const float*)d_in[13], (const float*)d_in[15],
        (const float*)d_in[17], (const float*)d_in[19], (const float*)d_in[21],
        bt);
    cudaStreamWaitEvent(0, ev[3], 0);
    embed_gemm<<<cdiv(N0v, 128), 256>>>(xh, bt + BT_EMBED, embed_b, feat0, N0v);

    // ---------- layer 0 (MT=64, 3 CTAs/SM) ----------
    cudaStreamWaitEvent(0, ev[1], 0);
    aggregate_w<<<n0 / 8, 256>>>(feat0, off0, sorted0, msg);
    igconv<64, 3><<<dim3(nbx0, 3), 256, IG_SMEM_64>>>(
        msg, feat0,
        bt + BT_L1F2, bt + BT_L1F1, bt + BT_L1F3, bt + BT_ATTN,
        (const float*)d_in[14], (const float*)d_in[12], (const float*)d_in[16],
        attn_b1, attn_w2, z, partial, beta, ctr0, 1.f / (float)N1v, N1v, nbx0);
    combine_gather<<<cdiv(N1v * 64, 256), 256>>>(
        (const __half2*)z, beta, (__half2*)feat1, N1v, N1v * 64);

    // ---------- layer 1 (MT=64, 3 CTAs/SM) ----------
    cudaStreamWaitEvent(0, ev[2], 0);
    aggregate_w<<<n1 / 8, 256>>>(feat1, off1, sorted1, msg);
    igconv<64, 3><<<dim3(nbx1, 3), 256, IG_SMEM_64>>>(
        msg, feat1,
        bt + BT_L2F2, bt + BT_L2F1, bt + BT_L2F3, bt + BT_ATTN,
        (const float*)d_in[20], (const float*)d_in[18], (const float*)d_in[22],
        attn_b1, attn_w2, z, partial, beta, ctr1, 1.f / (float)N2v, N2v, nbx1);
    combine_pred<<<N2v, 128>>>(z, beta, pred_w, pred_b, out, N2v, N2v * 128);
}

// round 17
// speedup vs baseline: 1.0232x; 1.0232x over previous
#include <cuda_runtime.h>
#include <cuda_fp16.h>
#include <math.h>
#include <stdint.h>

// ---------------- problem constants ----------------
#define N0v 100000
#define N1v 20000
#define N2v 4000
#define E0v 160000
#define E1v 64000

// ---------------- device scratch ----------------
__device__ __align__(16) __half g_feat0[(size_t)N0v * 256];
__device__ __align__(16) __half g_feat1[(size_t)N1v * 256];
__device__ __align__(16) __half g_msg[(size_t)3 * N1v * 768];
__device__ __align__(16) __half g_z[(size_t)3 * N1v * 128];
__device__ __align__(16) __half g_xh[(size_t)N0v * 128];
__device__ int    g_cnt0[3 * N1v];
__device__ int    g_off0[3 * N1v + 1];
__device__ int    g_cur0[3 * N1v];
__device__ int    g_sorted0[3 * E0v];
__device__ int    g_bsum0[128];
__device__ int    g_cnt1[3 * N2v];
__device__ int    g_off1[3 * N2v + 1];
__device__ int    g_cur1[3 * N2v];
__device__ int    g_sorted1[3 * E1v];
__device__ int    g_bsum1[128];
__device__ float  g_partial[8192];
__device__ float  g_beta[4];
__device__ int    g_ctr0;
__device__ int    g_ctr1;
__device__ __align__(16) __half g_bt[1015808];  // all weights, transposed fp16 K-major [128,K]

#define BT_EMBED 0
#define BT_ATTN  16384
#define BT_L1F1  32768
#define BT_L1F2  131072
#define BT_L1F3  425984
#define BT_L2F1  524288
#define BT_L2F2  622592
#define BT_L2F3  917504
#define BT_TOTAL 1015808

#define PAD  40    // pipeline tile row stride (halves)
#define INPS 264   // inpS row stride (halves)

__device__ __forceinline__ uint32_t smem_u32(const void* p) {
    uint32_t a;
    asm("{ .reg .u64 t; cvta.to.shared.u64 t, %1; cvt.u32.u64 %0, t; }" : "=r"(a) : "l"(p));
    return a;
}
__device__ __forceinline__ void mma_f16(float* d, const uint32_t* a, const uint32_t* b) {
    asm volatile(
        "mma.sync.aligned.m16n8k16.row.col.f32.f16.f16.f32 "
        "{%0,%1,%2,%3},{%4,%5,%6,%7},{%8,%9},{%0,%1,%2,%3};"
        : "+f"(d[0]), "+f"(d[1]), "+f"(d[2]), "+f"(d[3])
        : "r"(a[0]), "r"(a[1]), "r"(a[2]), "r"(a[3]), "r"(b[0]), "r"(b[1]));
}
__device__ __forceinline__ void ldsm_x4(uint32_t* r, uint32_t addr) {
    asm volatile("ldmatrix.sync.aligned.m8n8.x4.shared.b16 {%0,%1,%2,%3}, [%4];"
        : "=r"(r[0]), "=r"(r[1]), "=r"(r[2]), "=r"(r[3]) : "r"(addr));
}
__device__ __forceinline__ void ldsm_x2(uint32_t* r, uint32_t addr) {
    asm volatile("ldmatrix.sync.aligned.m8n8.x2.shared.b16 {%0,%1}, [%2];"
        : "=r"(r[0]), "=r"(r[1]) : "r"(addr));
}
__device__ __forceinline__ void cp16(uint32_t dst, const void* src, int sz) {
    asm volatile("cp.async.cg.shared.global [%0], [%1], 16, %2;"
        :: "r"(dst), "l"(src), "r"(sz));
}
#define CP_COMMIT() asm volatile("cp.async.commit_group;")

// ---------------- prep: all weights -> transposed fp16 table ----------------
__global__ void prep_all(const float* __restrict__ ew, const float* __restrict__ aw,
                         const float* __restrict__ f11, const float* __restrict__ f12,
                         const float* __restrict__ f13, const float* __restrict__ f21,
                         const float* __restrict__ f22, const float* __restrict__ f23,
                         __half* __restrict__ bt)
{
    int i = blockIdx.x * 256 + threadIdx.x;
    if (i >= BT_TOTAL) return;
    const float* w; int K; int rem;
    if (i < BT_ATTN)      { w = ew;  K = 128; rem = i - BT_EMBED; }
    else if (i < BT_L1F1) { w = aw;  K = 128; rem = i - BT_ATTN; }
    else if (i < BT_L1F2) { w = f11; K = 256; rem = i - BT_L1F1; }
    else if (i < BT_L1F3) { w = f12; K = 768; rem = i - BT_L1F2; }
    else if (i < BT_L2F1) { w = f13; K = 256; rem = i - BT_L1F3; }
    else if (i < BT_L2F2) { w = f21; K = 256; rem = i - BT_L2F1; }
    else if (i < BT_L2F3) { w = f22; K = 768; rem = i - BT_L2F2; }
    else                  { w = f23; K = 256; rem = i - BT_L2F3; }
    int per = 128 * K;
    int r = rem / per, j = rem - r * per;
    int n = j / K, k = j - n * K;
    bt[i] = __float2half_rn(w[(size_t)r * per + (size_t)k * 128 + n]);
}

// ---------------- fp32 -> fp16 vector convert ----------------
__global__ void cvt_x(const float4* __restrict__ x, __half2* __restrict__ xh, int n4)
{
    int i = blockIdx.x * 256 + threadIdx.x;
    if (i < n4) {
        float4 v = x[i];
        xh[2 * i]     = __floats2half2_rn(v.x, v.y);
        xh[2 * i + 1] = __floats2half2_rn(v.z, v.w);
    }
}

// ---------------- gather tss/rs into feat cols [128:256) ----------------
__global__ void gather_emb(const float* __restrict__ tss, const float* __restrict__ rs,
                           const int* __restrict__ nid, __half* __restrict__ feat, int n)
{
    int i = blockIdx.x * blockDim.x + threadIdx.x;
    int row = i >> 7, c = i & 127;
    if (row < n) {
        int g = nid[row];
        float v = (c < 64) ? tss[(size_t)g * 64 + c] : rs[(size_t)g * 64 + (c - 64)];
        feat[(size_t)row * 256 + 128 + c] = __float2half_rn(v);
    }
}

// ---------------- pipelined GEMM mainloops ----------------
template <int MT, int NTL>
__device__ __forceinline__ void gemm_gA(
    const __half* __restrict__ A, int lda, const __half* __restrict__ B, int K,
    int M, int m0, float acc[2][NTL][4], __half* pA, __half* pB,
    int tid, int wm, int wn, int a_m, int a_k, int b_n, int b_k)
{
    const int nt = K >> 5;
    const int lr = tid >> 2, lch = (tid & 3) * 8;
    const uint32_t pA0 = smem_u32(pA), pB0 = smem_u32(pB);
#pragma unroll
    for (int l = 0; l < MT / 64; l++) {
        int r = lr + l * 64;
        int gr = m0 + r;
        int sz = (gr < M) ? 16 : 0;
        cp16(pA0 + (r * PAD + lch) * 2, A + (size_t)(sz ? gr : m0) * lda + lch, sz);
    }
#pragma unroll
    for (int l = 0; l < 2; l++) {
        int r = lr + l * 64;
        cp16(pB0 + (r * PAD + lch) * 2, B + (size_t)r * K + lch, 16);
    }
    CP_COMMIT();
    for (int t = 0; t < nt; t++) {
        const int buf = t & 1;
        if (t + 1 < nt) {
            const int nb2 = (t + 1) & 1;
            int k0 = (t + 1) << 5;
#pragma unroll
            for (int l = 0; l < MT / 64; l++) {
                int r = lr + l * 64;
                int gr = m0 + r;
                int sz = (gr < M) ? 16 : 0;
                cp16(pA0 + (nb2 * MT * PAD + r * PAD + lch) * 2,
                     A + (size_t)(sz ? gr : m0) * lda + k0 + lch, sz);
            }
#pragma unroll
            for (int l = 0; l < 2; l++) {
                int r = lr + l * 64;
                cp16(pB0 + (nb2 * 128 * PAD + r * PAD + lch) * 2,
                     B + (size_t)r * K + k0 + lch, 16);
            }
            CP_COMMIT();
            asm volatile("cp.async.wait_group 1;");
        } else {
            asm volatile("cp.async.wait_group 0;");
        }
        __syncthreads();
#pragma unroll
        for (int ks = 0; ks < 2; ks++) {
            const int kk = ks * 16;
            uint32_t af[2][4];
#pragma unroll
            for (int mt = 0; mt < 2; mt++)
                ldsm_x4(af[mt], smem_u32(&pA[buf * MT * PAD + (wm * 32 + mt * 16 + a_m) * PAD + kk + a_k]));
#pragma unroll
            for (int ntl = 0; ntl < NTL; ntl++) {
                uint32_t bf[2];
                ldsm_x2(bf, smem_u32(&pB[buf * 128 * PAD + (wn * (NTL * 8) + ntl * 8 + b_n) * PAD + kk + b_k]));
#pragma unroll
                for (int mt = 0; mt < 2; mt++)
                    mma_f16(acc[mt][ntl], af[mt], bf);
            }
        }
        __syncthreads();
    }
}

// A resident in smem (inpS, stride INPS), BK=32 B pipeline
template <int MT, int NTL>
__device__ __forceinline__ void gemm_sA(
    const __half* sAfull, const __half* __restrict__ B, int K,
    float acc[2][NTL][4], __half* pB,
    int tid, int wm, int wn, int a_m, int a_k, int b_n, int b_k)
{
    const int nt = K >> 5;
    const int lr = tid >> 2, lch = (tid & 3) * 8;
    const uint32_t pB0 = smem_u32(pB);
#pragma unroll
    for (int l = 0; l < 2; l++) {
        int r = lr + l * 64;
        cp16(pB0 + (r * PAD + lch) * 2, B + (size_t)r * K + lch, 16);
    }
    CP_COMMIT();
    for (int t = 0; t < nt; t++) {
        const int buf = t & 1;
        if (t + 1 < nt) {
            const int nb2 = (t + 1) & 1;
            int k0 = (t + 1) << 5;
#pragma unroll
            for (int l = 0; l < 2; l++) {
                int r = lr + l * 64;
                cp16(pB0 + (nb2 * 128 * PAD + r * PAD + lch) * 2,
                     B + (size_t)r * K + k0 + lch, 16);
            }
            CP_COMMIT();
            asm volatile("cp.async.wait_group 1;");
        } else {
            asm volatile("cp.async.wait_group 0;");
        }
        __syncthreads();
#pragma unroll
        for (int ks = 0; ks < 2; ks++) {
            const int kk = ks * 16;
            uint32_t af[2][4];
#pragma unroll
            for (int mt = 0; mt < 2; mt++)
                ldsm_x4(af[mt], smem_u32(&sAfull[(wm * 32 + mt * 16 + a_m) * INPS + t * 32 + kk + a_k]));
#pragma unroll
            for (int ntl = 0; ntl < NTL; ntl++) {
                uint32_t bf[2];
                ldsm_x2(bf, smem_u32(&pB[buf * 128 * PAD + (wn * (NTL * 8) + ntl * 8 + b_n) * PAD + kk + b_k]));
#pragma unroll
                for (int mt = 0; mt < 2; mt++)
                    mma_f16(acc[mt][ntl], af[mt], bf);
            }
        }
        __syncthreads();
    }
}

#define ZERO_ACC(acc, NTL) do { \
    _Pragma("unroll") for (int _i = 0; _i < 2; _i++) \
    _Pragma("unroll") for (int _j = 0; _j < NTL; _j++) \
    _Pragma("unroll") for (int _q = 0; _q < 4; _q++) acc[_i][_j][_q] = 0.f; } while (0)

// ---------------- fused IGConv + attention dot + last-CTA beta ----------------
template <int MT>
__global__ void __launch_bounds__(256, 2) igconv(
    const __half* __restrict__ msg, const __half* __restrict__ feat,
    const __half* __restrict__ w2t, const __half* __restrict__ w1t,
    const __half* __restrict__ w3t, const __half* __restrict__ wat,
    const float* __restrict__ b2, const float* __restrict__ b1,
    const float* __restrict__ b3, const float* __restrict__ ba,
    const float* __restrict__ w2a,
    __half* __restrict__ z, float* __restrict__ partial,
    float* __restrict__ beta_out, int* __restrict__ ctr, float invN,
    int M, int nbx)
{
    constexpr int NWM = MT / 32;
    constexpr int NWN = 8 / NWM;
    constexpr int NTL = 128 / (NWN * 8);

    extern __shared__ __half sm[];
    __half* inpS = sm;                         // MT x INPS
    __half* pA   = sm + MT * INPS;             // 2 x MT x PAD
    __half* pB   = pA + 2 * MT * PAD;          // 2 x 128 x PAD
    float* rowsum = (float*)pA;

    __shared__ float bsh[3];
    __shared__ int lastFlag;

    const int tid = threadIdx.x, wid = tid >> 5, lane = tid & 31;
    const int wm = wid & (NWM - 1), wn = wid / NWM;
    const int rrel = blockIdx.y;
    const int m0 = blockIdx.x * MT;
    const int a_m = (lane & 7) + ((lane >> 3) & 1) * 8;
    const int a_k = (lane >> 4) * 8;
    const int bln = lane & 15;
    const int b_n = bln & 7;
    const int b_k = ((bln >> 3) & 1) * 8;
    const int fr = lane >> 2, fc = (lane & 3) * 2;

    float acc[2][NTL][4];

    // ---- stage 1: fc2 (msg @ W2) -> relu -> inpS[:,0:128) ----
    ZERO_ACC(acc, NTL);
    gemm_gA<MT, NTL>(msg + (size_t)rrel * M * 768, 768, w2t + (size_t)rrel * 128 * 768, 768,
                     M, m0, acc, pA, pB, tid, wm, wn, a_m, a_k, b_n, b_k);
    {
        const float* bb = b2 + rrel * 128;
#pragma unroll
        for (int mt = 0; mt < 2; mt++)
#pragma unroll
            for (int hf = 0; hf < 2; hf++) {
                int row = wm * 32 + mt * 16 + fr + hf * 8;
#pragma unroll
                for (int ntl = 0; ntl < NTL; ntl++) {
                    int gc = wn * (NTL * 8) + ntl * 8 + fc;
                    float vx = fmaxf(acc[mt][ntl][hf * 2 + 0] + bb[gc + 0], 0.f);
                    float vy = fmaxf(acc[mt][ntl][hf * 2 + 1] + bb[gc + 1], 0.f);
                    *(__half2*)&inpS[row * INPS + gc] = __floats2half2_rn(vx, vy);
                }
            }
    }

    // ---- stage 2: fc1 (feat @ W1) -> relu -> inpS[:,128:256) ----
    ZERO_ACC(acc, NTL);
    gemm_gA<MT, NTL>(feat, 256, w1t + (size_t)rrel * 128 * 256, 256,
                     M, m0, acc, pA, pB, tid, wm, wn, a_m, a_k, b_n, b_k);
    {
        const float* bb = b1 + rrel * 128;
#pragma unroll
        for (int mt = 0; mt < 2; mt++)
#pragma unroll
            for (int hf = 0; hf < 2; hf++) {
                int row = wm * 32 + mt * 16 + fr + hf * 8;
#pragma unroll
                for (int ntl = 0; ntl < NTL; ntl++) {
                    int gc = wn * (NTL * 8) + ntl * 8 + fc;
                    float vx = fmaxf(acc[mt][ntl][hf * 2 + 0] + bb[gc + 0], 0.f);
                    float vy = fmaxf(acc[mt][ntl][hf * 2 + 1] + bb[gc + 1], 0.f);
                    *(__half2*)&inpS[row * INPS + 128 + gc] = __floats2half2_rn(vx, vy);
                }
            }
    }
    __syncthreads();

    // ---- stage 3: fc3 (inpS @ W3) -> z (fp16) + zh into inpS[:,0:128) ----
    ZERO_ACC(acc, NTL);
    gemm_sA<MT, NTL>(inpS, w3t + (size_t)rrel * 128 * 256, 256,
                     acc, pB, tid, wm, wn, a_m, a_k, b_n, b_k);
    {
        const float* bb = b3 + rrel * 128;
        __half* zr = z + (size_t)rrel * M * 128;
#pragma unroll
        for (int mt = 0; mt < 2; mt++)
#pragma unroll
            for (int hf = 0; hf < 2; hf++) {
                int row = wm * 32 + mt * 16 + fr + hf * 8;
                int gr = m0 + row;
#pragma unroll
                for (int ntl = 0; ntl < NTL; ntl++) {
                    int gc = wn * (NTL * 8) + ntl * 8 + fc;
                    float vx = acc[mt][ntl][hf * 2 + 0] + bb[gc + 0];
                    float vy = acc[mt][ntl][hf * 2 + 1] + bb[gc + 1];
                    __half2 h = __floats2half2_rn(vx, vy);
                    if (gr < M) *(__half2*)&zr[(size_t)gr * 128 + gc] = h;
                    *(__half2*)&inpS[row * INPS + gc] = h;
                }
            }
    }
    __syncthreads();

    // ---- stage 4: attention (zh @ attnW1) -> tanh -> dot w2 -> partial ----
    ZERO_ACC(acc, NTL);
    gemm_sA<MT, NTL>(inpS, wat, 128, acc, pB, tid, wm, wn, a_m, a_k, b_n, b_k);
#pragma unroll
    for (int mt = 0; mt < 2; mt++)
#pragma unroll
        for (int hf = 0; hf < 2; hf++) {
            int row = wm * 32 + mt * 16 + fr + hf * 8;
            int gr = m0 + row;
            float acc_s = 0.f;
            if (gr < M) {
#pragma unroll
                for (int ntl = 0; ntl < NTL; ntl++) {
                    int gc = wn * (NTL * 8) + ntl * 8 + fc;
                    float vx = tanhf(acc[mt][ntl][hf * 2 + 0] + ba[gc + 0]);
                    float vy = tanhf(acc[mt][ntl][hf * 2 + 1] + ba[gc + 1]);
                    acc_s += vx * w2a[gc] + vy * w2a[gc + 1];
                }
            }
            float v = acc_s;
            v += __shfl_xor_sync(0xFFFFFFFFu, v, 1);
            v += __shfl_xor_sync(0xFFFFFFFFu, v, 2);
            if ((lane & 3) == 0) rowsum[wn * MT + row] = v;
        }
    __syncthreads();
    if (wid == 0) {
        float tot = 0.f;
        for (int i = lane; i < NWN * MT; i += 32) tot += rowsum[i];
#pragma unroll
        for (int o = 16; o; o >>= 1) tot += __shfl_xor_sync(0xFFFFFFFFu, tot, o);
        if (!lane) {
            partial[rrel * nbx + blockIdx.x] = tot;
            __threadfence();
            int old = atomicAdd(ctr, 1);
            lastFlag = (old == 3 * nbx - 1) ? 1 : 0;
        }
    }
    __syncthreads();
    if (lastFlag) {
        __threadfence();
        if (tid < 3) {
            float s = 0.f;
            for (int i = 0; i < nbx; i++) s += partial[tid * nbx + i];
            bsh[tid] = s * invN;
        }
        __syncthreads();
        if (tid == 0) {
            float m = fmaxf(bsh[0], fmaxf(bsh[1], bsh[2]));
            float e0 = expf(bsh[0] - m), e1 = expf(bsh[1] - m), e2 = expf(bsh[2] - m);
            float inv = 1.f / (e0 + e1 + e2);
            beta_out[0] = e0 * inv; beta_out[1] = e1 * inv; beta_out[2] = e2 * inv;
            *ctr = 0;
            __threadfence();
        }
    }
}

// ---------------- embed HGEMM (fp16 A, cp.async; cols [0:128) only) ----------------
__global__ void __launch_bounds__(256, 2) embed_gemm(
    const __half* __restrict__ A, const __half* __restrict__ B,
    const float* __restrict__ bias, __half* __restrict__ C, int M)
{
    __shared__ __align__(16) __half sA[2][128 * PAD];
    __shared__ __align__(16) __half sB[2][128 * PAD];
    const int tid = threadIdx.x, wid = tid >> 5, lane = tid & 31;
    const int wm = wid & 3, wn = wid >> 2;
    const int m0 = blockIdx.x * 128;
    const int a_m = (lane & 7) + ((lane >> 3) & 1) * 8;
    const int a_k = (lane >> 4) * 8;
    const int bln = lane & 15;
    const int b_n = bln & 7;
    const int b_k = ((bln >> 3) & 1) * 8;
    float acc[2][8][4];
    ZERO_ACC(acc, 8);
    gemm_gA<128, 8>(A, 128, B, 128, M, m0, acc, sA[0], sB[0], tid, wm, wn, a_m, a_k, b_n, b_k);
    const int fr = lane >> 2, fc = (lane & 3) * 2;
#pragma unroll
    for (int mt = 0; mt < 2; mt++)
#pragma unroll
        for (int hf = 0; hf < 2; hf++) {
            int gr = m0 + wm * 32 + mt * 16 + fr + hf * 8;
            if (gr >= M) continue;
#pragma unroll
            for (int ntl = 0; ntl < 8; ntl++) {
                int gc = wn * 64 + ntl * 8 + fc;
                float vx = acc[mt][ntl][hf * 2 + 0] + bias[gc + 0];
                float vy = acc[mt][ntl][hf * 2 + 1] + bias[gc + 1];
                *(__half2*)&C[(size_t)gr * 256 + gc] = __floats2half2_rn(vx, vy);
            }
        }
}

// ---------------- CSR build ----------------
__global__ void hist_k(const int* __restrict__ dst, int* __restrict__ cnt, int E, int ndst)
{
    int e = blockIdx.x * blockDim.x + threadIdx.x;
    if (e < 3 * E) atomicAdd(&cnt[(e / E) * ndst + dst[e]], 1);
}
__global__ void scan_part(const int* __restrict__ cnt, int* __restrict__ off,
                          int* __restrict__ bsum, int n)
{
    __shared__ int ws[32];
    int tid = threadIdx.x, lane = tid & 31, w = tid >> 5;
    int i = blockIdx.x * 1024 + tid;
    int v = (i < n) ? cnt[i] : 0;
    int x = v;
#pragma unroll
    for (int o = 1; o < 32; o <<= 1) {
        int t = __shfl_up_sync(0xFFFFFFFFu, x, o);
        if (lane >= o) x += t;
    }
    if (lane == 31) ws[w] = x;
    __syncthreads();
    if (w == 0) {
        int y = ws[lane];
#pragma unroll
        for (int o = 1; o < 32; o <<= 1) {
            int t = __shfl_up_sync(0xFFFFFFFFu, y, o);
            if (lane >= o) y += t;
        }
        ws[lane] = y;
    }
    __syncthreads();
    int excl = x - v + (w ? ws[w - 1] : 0);
    if (i < n) off[i] = excl;
    if (tid == 1023) bsum[blockIdx.x] = excl + v;
}
__global__ void scan_bs(int* __restrict__ bsum, int* __restrict__ off, int nb, int n)
{
    __shared__ int sh[64];
    int tid = threadIdx.x;
    int v = (tid < nb) ? bsum[tid] : 0;
    sh[tid] = v;
    __syncthreads();
    for (int d = 1; d < 64; d <<= 1) {
        int t = (tid >= d) ? sh[tid - d] : 0;
        __syncthreads();
        sh[tid] += t;
        __syncthreads();
    }
    if (tid < nb) bsum[tid] = sh[tid] - v;
    if (tid == 0) off[n] = sh[63];
}
__global__ void scan_add(int* __restrict__ off, const int* __restrict__ bsum,
                         int* __restrict__ cur, int n)
{
    int i = blockIdx.x * 1024 + threadIdx.x;
    if (i < n) {
        int o = off[i] + bsum[blockIdx.x];
        off[i] = o;
        cur[i] = o;
    }
}
__global__ void scatter_k(const int* __restrict__ src, const int* __restrict__ dst,
                          int* __restrict__ cur, int* __restrict__ sorted, int E, int ndst)
{
    int e = blockIdx.x * blockDim.x + threadIdx.x;
    if (e < 3 * E) {
        int p = atomicAdd(&cur[(e / E) * ndst + dst[e]], 1);
        sorted[p] = src[e];
    }
}

// ---------------- aggregation: warp per (rel,dst); 2-way MLP unroll, order-preserving ----------------
#define DEGCAP 96
__global__ void aggregate_w(const __half* __restrict__ feat, const int* __restrict__ off,
                            const int* __restrict__ sorted, __half* __restrict__ msg)
{
    __shared__ int idx[8][DEGCAP];
    int ws = threadIdx.x >> 5, lane = threadIdx.x & 31;
    int b = blockIdx.x * 8 + ws;
    int s0 = off[b];
    int deg = off[b + 1] - s0;
    if (deg > DEGCAP) deg = DEGCAP;
    for (int i = lane; i < deg; i += 32) idx[ws][i] = sorted[s0 + i];
    __syncwarp();
    for (int p = 0; p < deg; p++) {
        for (int j = (p & 1) + 2 * lane; j + 1 < deg; j += 64) {
            int a = idx[ws][j], c = idx[ws][j + 1];
            if (a > c) { idx[ws][j] = c; idx[ws][j + 1] = a; }
        }
        __syncwarp();
    }
    float sum[8], mx[8];
#pragma unroll
    for (int q = 0; q < 8; q++) { sum[q] = 0.f; mx[q] = -INFINITY; }
    int i = 0;
    for (; i + 1 < deg; i += 2) {
        // two independent loads issued back-to-back (doubled MLP), accumulated in order
        uint4 v0 = *(const uint4*)(feat + (size_t)idx[ws][i] * 256 + lane * 8);
        uint4 v1 = *(const uint4*)(feat + (size_t)idx[ws][i + 1] * 256 + lane * 8);
        __half2* h0 = (__half2*)&v0;
        __half2* h1 = (__half2*)&v1;
#pragma unroll
        for (int q = 0; q < 4; q++) {
            float2 f = __half22float2(h0[q]);
            sum[2 * q]     += f.x;
            sum[2 * q + 1] += f.y;
            mx[2 * q]       = fmaxf(mx[2 * q], f.x);
            mx[2 * q + 1]   = fmaxf(mx[2 * q + 1], f.y);
        }
#pragma unroll
        for (int q = 0; q < 4; q++) {
            float2 f = __half22float2(h1[q]);
            sum[2 * q]     += f.x;
            sum[2 * q + 1] += f.y;
            mx[2 * q]       = fmaxf(mx[2 * q], f.x);
            mx[2 * q + 1]   = fmaxf(mx[2 * q + 1], f.y);
        }
    }
    if (i < deg) {
        uint4 v = *(const uint4*)(feat + (size_t)idx[ws][i] * 256 + lane * 8);
        __half2* h = (__half2*)&v;
#pragma unroll
        for (int q = 0; q < 4; q++) {
            float2 f = __half22float2(h[q]);
            sum[2 * q]     += f.x;
            sum[2 * q + 1] += f.y;
            mx[2 * q]       = fmaxf(mx[2 * q], f.x);
            mx[2 * q + 1]   = fmaxf(mx[2 * q + 1], f.y);
        }
    }
    float inv = deg ? 1.f / (float)deg : 0.f;
    if (!deg) {
#pragma unroll
        for (int q = 0; q < 8; q++) mx[q] = 0.f;
    }
    __half2 omx[4], omean[4], osum[4];
#pragma unroll
    for (int q = 0; q < 4; q++) {
        omx[q]   = __floats2half2_rn(mx[2 * q], mx[2 * q + 1]);
        omean[q] = __floats2half2_rn(sum[2 * q] * inv, sum[2 * q + 1] * inv);
        osum[q]  = __floats2half2_rn(sum[2 * q], sum[2 * q + 1]);
    }
    size_t base = (size_t)b * 768 + lane * 8;
    *(uint4*)(msg + base)       = *(uint4*)omx;
    *(uint4*)(msg + base + 256) = *(uint4*)omean;
    *(uint4*)(msg + base + 512) = *(uint4*)osum;
}

// ---------------- layer0 combine (vectorized: 2 cols/thread) ----------------
__global__ void combine_gather(const __half2* __restrict__ z, const float* __restrict__ beta,
                               __half2* __restrict__ feat, int n, int zstride2)
{
    int i = blockIdx.x * blockDim.x + threadIdx.x;   // n*64 jobs
    int row = i >> 6, c2 = i & 63;
    if (row >= n) return;
    float b0 = __ldg(&beta[0]), b1 = __ldg(&beta[1]), b2 = __ldg(&beta[2]);
    size_t o = (size_t)row * 64 + c2;
    float2 z0 = __half22float2(z[o]);
    float2 z1 = __half22float2(z[o + (size_t)zstride2]);
    float2 z2 = __half22float2(z[o + 2 * (size_t)zstride2]);
    float vx = fmaxf(b0 * z0.x + b1 * z1.x + b2 * z2.x, 0.f);
    float vy = fmaxf(b0 * z0.y + b1 * z1.y + b2 * z2.y, 0.f);
    feat[(size_t)row * 128 + c2] = __floats2half2_rn(vx, vy);
}

// ---------------- layer1 combine + predictor ----------------
__global__ void combine_pred(const __half* __restrict__ z, const float* __restrict__ beta,
                             const float* __restrict__ pw, const float* __restrict__ pb,
                             float* __restrict__ out, int n, int zstride)
{
    __shared__ float sh[4];
    int row = blockIdx.x, c = threadIdx.x;
    float b0 = __ldg(&beta[0]), b1 = __ldg(&beta[1]), b2 = __ldg(&beta[2]);
    size_t o = (size_t)row * 128 + c;
    float v = b0 * __half2float(z[o]) + b1 * __half2float(z[o + (size_t)zstride])
            + b2 * __half2float(z[o + 2 * (size_t)zstride]);
    float s = v * pw[c];
    int lane = c & 31, w = c >> 5;
#pragma unroll
    for (int of = 16; of; of >>= 1) s += __shfl_xor_sync(0xFFFFFFFFu, s, of);
    if (!lane) sh[w] = s;
    __syncthreads();
    if (c == 0) {
        float tot = sh[0] + sh[1] + sh[2] + sh[3];
        out[row] = 1.f / (1.f + expf(-(tot + pb[0])));
    }
}

// ---------------- host orchestration ----------------
static inline int cdiv(int a, int b) { return (a + b - 1) / b; }
#define IG_SMEM_128 ((128 * INPS + 2 * 128 * PAD + 2 * 128 * PAD) * 2)
#define IG_SMEM_64  ((64 * INPS + 2 * 64 * PAD + 2 * 128 * PAD) * 2)

extern "C" void kernel_launch(void* const* d_in, const int* in_sizes, int n_in,
                              void* d_out, int out_size)
{
    const float* x_user   = (const float*)d_in[0];
    const float* tss      = (const float*)d_in[1];
    const float* rs       = (const float*)d_in[2];
    const int*   src_nid0 = (const int*)d_in[3];
    const int*   src_nid1 = (const int*)d_in[4];
    const int*   e0_src   = (const int*)d_in[5];
    const int*   e0_dst   = (const int*)d_in[6];
    const int*   e1_src   = (const int*)d_in[7];
    const int*   e1_dst   = (const int*)d_in[8];
    const float* embed_w  = (const float*)d_in[9];
    const float* embed_b  = (const float*)d_in[10];
    const float* attn_w1  = (const float*)d_in[23];
    const float* attn_b1  = (const float*)d_in[24];
    const float* attn_w2  = (const float*)d_in[25];
    const float* pred_w   = (const float*)d_in[26];
    const float* pred_b   = (const float*)d_in[27];
    float* out = (float*)d_out;

    __half *feat0, *feat1, *msg, *bt, *xh, *z;
    float *partial, *beta;
    int *ctr0, *ctr1;
    int *cnt0, *off0, *cur0, *sorted0, *bsum0;
    int *cnt1, *off1, *cur1, *sorted1, *bsum1;
    cudaGetSymbolAddress((void**)&feat0, g_feat0);
    cudaGetSymbolAddress((void**)&feat1, g_feat1);
    cudaGetSymbolAddress((void**)&msg, g_msg);
    cudaGetSymbolAddress((void**)&z, g_z);
    cudaGetSymbolAddress((void**)&xh, g_xh);
    cudaGetSymbolAddress((void**)&partial, g_partial);
    cudaGetSymbolAddress((void**)&beta, g_beta);
    cudaGetSymbolAddress((void**)&ctr0, g_ctr0);
    cudaGetSymbolAddress((void**)&ctr1, g_ctr1);
    cudaGetSymbolAddress((void**)&cnt0, g_cnt0);
    cudaGetSymbolAddress((void**)&off0, g_off0);
    cudaGetSymbolAddress((void**)&cur0, g_cur0);
    cudaGetSymbolAddress((void**)&sorted0, g_sorted0);
    cudaGetSymbolAddress((void**)&bsum0, g_bsum0);
    cudaGetSymbolAddress((void**)&cnt1, g_cnt1);
    cudaGetSymbolAddress((void**)&off1, g_off1);
    cudaGetSymbolAddress((void**)&cur1, g_cur1);
    cudaGetSymbolAddress((void**)&sorted1, g_sorted1);
    cudaGetSymbolAddress((void**)&bsum1, g_bsum1);
    cudaGetSymbolAddress((void**)&bt, g_bt);

    static cudaStream_t sA = 0, sB = 0;
    static cudaEvent_t ev[8];
    static bool init = false;
    if (!init) {
        cudaStreamCreateWithFlags(&sA, cudaStreamNonBlocking);
        cudaStreamCreateWithFlags(&sB, cudaStreamNonBlocking);
        for (int i = 0; i < 8; i++) cudaEventCreateWithFlags(&ev[i], cudaEventDisableTiming);
        cudaFuncSetAttribute(igconv<128>, cudaFuncAttributeMaxDynamicSharedMemorySize, IG_SMEM_128);
        cudaFuncSetAttribute(igconv<64>, cudaFuncAttributeMaxDynamicSharedMemorySize, IG_SMEM_64);
        init = true;
    }

    const int n0 = 3 * N1v, nb0 = cdiv(n0, 1024);
    const int n1 = 3 * N2v, nb1 = cdiv(n1, 1024);
    const int nbx0 = cdiv(N1v, 128), nbx1 = cdiv(N2v, 64);

    // fork
    cudaEventRecord(ev[0], 0);
    cudaStreamWaitEvent(sA, ev[0], 0);
    cudaStreamWaitEvent(sB, ev[0], 0);

    // sA: x convert -> feat0 gather (cols [128:256)) -> CSR0
    cvt_x<<<cdiv(N0v * 128 / 4, 256), 256, 0, sA>>>(
        (const float4*)x_user, (__half2*)xh, N0v * 128 / 4);
    cudaEventRecord(ev[3], sA);
    gather_emb<<<cdiv(N0v * 128, 256), 256, 0, sA>>>(tss, rs, src_nid0, feat0, N0v);
    cudaMemsetAsync(cnt0, 0, n0 * sizeof(int), sA);
    hist_k<<<cdiv(3 * E0v, 256), 256, 0, sA>>>(e0_dst, cnt0, E0v, N1v);
    scan_part<<<nb0, 1024, 0, sA>>>(cnt0, off0, bsum0, n0);
    scan_bs<<<1, 64, 0, sA>>>(bsum0, off0, nb0, n0);
    scan_add<<<nb0, 1024, 0, sA>>>(off0, bsum0, cur0, n0);
    scatter_k<<<cdiv(3 * E0v, 256), 256, 0, sA>>>(e0_src, e0_dst, cur0, sorted0, E0v, N1v);
    cudaEventRecord(ev[1], sA);   // CSR0 + feat0 gather done

    // sB: feat1 gather (cols [128:256)) -> CSR1
    gather_emb<<<cdiv(N1v * 128, 256), 256, 0, sB>>>(tss, rs, src_nid1, feat1, N1v);
    cudaMemsetAsync(cnt1, 0, n1 * sizeof(int), sB);
    hist_k<<<cdiv(3 * E1v, 256), 256, 0, sB>>>(e1_dst, cnt1, E1v, N2v);
    scan_part<<<nb1, 1024, 0, sB>>>(cnt1, off1, bsum1, n1);
    scan_bs<<<1, 64, 0, sB>>>(bsum1, off1, nb1, n1);
    scan_add<<<nb1, 1024, 0, sB>>>(off1, bsum1, cur1, n1);
    scatter_k<<<cdiv(3 * E1v, 256), 256, 0, sB>>>(e1_src, e1_dst, cur1, sorted1, E1v, N2v);
    cudaEventRecord(ev[2], sB);   // CSR1 + feat1 gather done

    // stream 0: weight prep; embed GEMM (cols [0:128) only)
    prep_all<<<cdiv(BT_TOTAL, 256), 256>>>(
        embed_w, attn_w1,
        (const float*)d_in[11], (const float*)d_in[13], (const float*)d_in[15],
        (const float*)d_in[17], (const float*)d_in[19], (const float*)d_in[21],
        bt);
    cudaStreamWaitEvent(0, ev[3], 0);
    embed_gemm<<<cdiv(N0v, 128), 256>>>(xh, bt + BT_EMBED, embed_b, feat0, N0v);

    // ---------- layer 0 (MT=128) ----------
    cudaStreamWaitEvent(0, ev[1], 0);
    aggregate_w<<<n0 / 8, 256>>>(feat0, off0, sorted0, msg);
    igconv<128><<<dim3(nbx0, 3), 256, IG_SMEM_128>>>(
        msg, feat0,
        bt + BT_L1F2, bt + BT_L1F1, bt + BT_L1F3, bt + BT_ATTN,
        (const float*)d_in[14], (const float*)d_in[12], (const float*)d_in[16],
        attn_b1, attn_w2, z, partial, beta, ctr0, 1.f / (float)N1v, N1v, nbx0);
    combine_gather<<<cdiv(N1v * 64, 256), 256>>>(
        (const __half2*)z, beta, (__half2*)feat1, N1v, N1v * 64);

    // ---------- layer 1 (MT=64) ----------
    cudaStreamWaitEvent(0, ev[2], 0);
    aggregate_w<<<n1 / 8, 256>>>(feat1, off1, sorted1, msg);
    igconv<64><<<dim3(nbx1, 3), 256, IG_SMEM_64>>>(
        msg, feat1,
        bt + BT_L2F2, bt + BT_L2F1, bt + BT_L2F3, bt + BT_ATTN,
        (const float*)d_in[20], (const float*)d_in[18], (const float*)d_in[22],
        attn_b1, attn_w2, z, partial, beta, ctr1, 1.f / (float)N2v, N2v, nbx1);
    combine_pred<<<N2v, 128>>>(z, beta, pred_w, pred_b, out, N2v, N2v * 128);
}